// round 16
// baseline (speedup 1.0000x reference)
#include <cuda_runtime.h>
#include <cuda_bf16.h>
#include <mma.h>
#include <cstdint>
#include <cstddef>

using namespace nvcuda;

// Problem constants
#define BB 2
#define LL 1024
#define HH 2048
#define HD 64
#define NQ 32
#define NK 4
#define NPREV 28

// Scratch (device globals)
__device__ float g_Q[(size_t)BB * NQ * LL * HD];
__device__ float g_K[(size_t)BB * NQ * LL * HD];
__device__ float g_V[(size_t)BB * NQ * LL * HD];
__device__ float g_AO[(size_t)BB * LL * (NQ * HD)];
// Pre-converted (tf32-rounded) GEMM operands
__device__ float g_hsT[(size_t)BB * LL * HH];
__device__ float g_WqT[(size_t)NQ * HD * HH];
__device__ float g_WkT[(size_t)NK * HD * HH];
__device__ float g_WvT[(size_t)NK * HD * HH];
__device__ float g_WoT[(size_t)HH * NQ * HD];

// ---------------------------------------------------------------------------
// cp.async helpers
// ---------------------------------------------------------------------------
__device__ __forceinline__ void cp_async16(uint32_t smem, const void* gmem) {
    asm volatile("cp.async.cg.shared.global [%0], [%1], 16;\n"
                 :: "r"(smem), "l"(gmem));
}
__device__ __forceinline__ void cp_commit() {
    asm volatile("cp.async.commit_group;\n" ::: "memory");
}
template<int N> __device__ __forceinline__ void cp_wait() {
    asm volatile("cp.async.wait_group %0;\n" :: "n"(N) : "memory");
}

// ---------------------------------------------------------------------------
// tf32 rounding convert kernel
// ---------------------------------------------------------------------------
__global__ void cvt_tf32(const float4* __restrict__ src, float4* __restrict__ dst,
                         int n4)
{
    int i = blockIdx.x * blockDim.x + threadIdx.x;
    int stride = gridDim.x * blockDim.x;
    for (; i < n4; i += stride) {
        float4 v = src[i];
        v.x = wmma::__float_to_tf32(v.x);
        v.y = wmma::__float_to_tf32(v.y);
        v.z = wmma::__float_to_tf32(v.z);
        v.w = wmma::__float_to_tf32(v.w);
        dst[i] = v;
    }
}

// ---------------------------------------------------------------------------
// 4-stage cp.async TF32 GEMM (R15-proven). C = A @ W^T.
// ---------------------------------------------------------------------------
#define LDS 20

template<int BM, int BN, int WM, int WN, int MODE>
__global__ void __launch_bounds__(256, 2) gemm_ca(
    const float* __restrict__ A, const float* __restrict__ W1,
    const float* __restrict__ W2, float* __restrict__ C1,
    float* __restrict__ C2, int M, int N, int K)
{
    constexpr int S    = 4;
    constexpr int MI   = BM / (16 * WM);
    constexpr int NJ   = BN / (16 * WN);
    constexpr int APT  = BM / 64;
    constexpr int BPT  = BN / 64;
    constexpr int ABUF = BM * LDS;
    constexpr int BBUF = BN * LDS;

    extern __shared__ float gsm[];
    float* As = gsm;
    float* Bs = gsm + S * ABUF;

    const int t    = threadIdx.x;
    const int warp = t >> 5;
    const int wm   = warp % WM;
    const int wn   = warp / WM;
    const int row0 = blockIdx.y * BM;
    const int col0 = blockIdx.x * BN;

    const float* aptr[APT];
    uint32_t aoff[APT];
#pragma unroll
    for (int q = 0; q < APT; q++) {
        int f = q * 256 + t;
        int r = f >> 2, c = (f & 3) * 4;
        aptr[q] = A + (size_t)(row0 + r) * K + c;
        aoff[q] = (uint32_t)__cvta_generic_to_shared(&As[r * LDS + c]);
    }
    const float* bptr[BPT];
    uint32_t boff[BPT];
#pragma unroll
    for (int q = 0; q < BPT; q++) {
        int f = q * 256 + t;
        int r = f >> 2, c = (f & 3) * 4;
        int rw = col0 + r;
        const float* src;
        if (MODE == 2) src = (rw < 256) ? (W1 + (size_t)rw * K)
                                        : (W2 + (size_t)(rw - 256) * K);
        else           src = W1 + (size_t)rw * K;
        bptr[q] = src + c;
        boff[q] = (uint32_t)__cvta_generic_to_shared(&Bs[r * LDS + c]);
    }

    wmma::fragment<wmma::accumulator, 16, 16, 8, float> acc[MI][NJ];
#pragma unroll
    for (int i = 0; i < MI; i++)
#pragma unroll
        for (int j = 0; j < NJ; j++) wmma::fill_fragment(acc[i][j], 0.0f);

    auto issue = [&](int chunk) {
        int st = chunk & (S - 1);
        int bk = chunk * 16;
#pragma unroll
        for (int q = 0; q < APT; q++)
            cp_async16(aoff[q] + st * ABUF * 4, aptr[q] + bk);
#pragma unroll
        for (int q = 0; q < BPT; q++)
            cp_async16(boff[q] + st * BBUF * 4, bptr[q] + bk);
    };
    auto compute = [&](int st) {
        const float* Ab = As + st * ABUF;
        const float* Bb = Bs + st * BBUF;
#pragma unroll
        for (int ks = 0; ks < 2; ks++) {
            wmma::fragment<wmma::matrix_a, 16, 16, 8, wmma::precision::tf32,
                           wmma::row_major> af[MI];
#pragma unroll
            for (int i = 0; i < MI; i++)
                wmma::load_matrix_sync(af[i],
                    Ab + (wm * MI + i) * 16 * LDS + ks * 8, LDS);
#pragma unroll
            for (int j = 0; j < NJ; j++) {
                wmma::fragment<wmma::matrix_b, 16, 16, 8, wmma::precision::tf32,
                               wmma::col_major> bf;
                wmma::load_matrix_sync(bf,
                    Bb + (wn * NJ + j) * 16 * LDS + ks * 8, LDS);
#pragma unroll
                for (int i = 0; i < MI; i++)
                    wmma::mma_sync(acc[i][j], af[i], bf, acc[i][j]);
            }
        }
    };

    const int nit = K / 16;
    issue(0); cp_commit();
    issue(1); cp_commit();
    issue(2); cp_commit();
    for (int i = 0; i < nit; i++) {
        cp_wait<S - 2>();
        __syncthreads();
        if (i + S - 1 < nit) issue(i + S - 1);
        cp_commit();
        compute(i & (S - 1));
    }

#pragma unroll
    for (int i = 0; i < MI; i++) {
        int m0 = row0 + (wm * MI + i) * 16;
#pragma unroll
        for (int j = 0; j < NJ; j++) {
            int n0 = col0 + (wn * NJ + j) * 16;
            if (MODE == 0) {
                wmma::store_matrix_sync(C1 + (size_t)m0 * N + n0, acc[i][j], N,
                                        wmma::mem_row_major);
            } else if (MODE == 1) {
                int b = m0 >> 10, l = m0 & 1023;
                int h = n0 >> 6,  d = n0 & 63;
                float* dst = C1 + ((size_t)((b * 32 + h) * 1024 + l)) * 64 + d;
                wmma::store_matrix_sync(dst, acc[i][j], 64, wmma::mem_row_major);
            } else {
                int b = m0 >> 10, l = m0 & 1023;
                int h = n0 >> 6,  d = n0 & 63;
                if (h < 4) {
                    float* dst = C1 + ((size_t)((b * 32 + NPREV + h) * 1024 + l)) * 64 + d;
                    wmma::store_matrix_sync(dst, acc[i][j], 64, wmma::mem_row_major);
                } else {
#pragma unroll
                    for (int e = 0; e < acc[i][j].num_elements; e++)
                        acc[i][j].x[e] = wmma::__float_to_tf32(acc[i][j].x[e]);
                    float* dst = C2 + ((size_t)((b * 32 + NPREV + h - 4) * 1024 + l)) * 64 + d;
                    wmma::store_matrix_sync(dst, acc[i][j], 64, wmma::mem_row_major);
                }
            }
        }
    }
}

// ---------------------------------------------------------------------------
// RoPE + cache gather (tf32-rounded stores)
// ---------------------------------------------------------------------------
__global__ void __launch_bounds__(256) rope_gather_kernel(
    const float* __restrict__ prev_k, const float* __restrict__ prev_v,
    const float* __restrict__ cosp,   const float* __restrict__ sinp)
{
    unsigned t = blockIdx.x * 256u + threadIdx.x;
    int d = t & 31;
    int l = (t >> 5) & 1023;
    int h = (t >> 15) & 31;
    int b = t >> 20;

    float c = cosp[l * 64 + d];
    float s = sinp[l * 64 + d];

    size_t base = ((size_t)(b * 32 + h) * 1024 + l) * 64;

    {
        float* q = g_Q + base;
        float x1 = q[d], x2 = q[d + 32];
        q[d]      = wmma::__float_to_tf32(x1 * c - x2 * s);
        q[d + 32] = wmma::__float_to_tf32(x2 * c + x1 * s);
    }
    {
        float* k = g_K + base;
        float y1, y2;
        if (h < NPREV) {
            const float* pk = prev_k + ((size_t)(b * NPREV + h) * 1024 + l) * 64;
            y1 = pk[d]; y2 = pk[d + 32];
        } else {
            y1 = k[d]; y2 = k[d + 32];
        }
        k[d]      = wmma::__float_to_tf32(y1 * c - y2 * s);
        k[d + 32] = wmma::__float_to_tf32(y2 * c + y1 * s);
    }
    if (h < NPREV) {
        const float* pv = prev_v + ((size_t)(b * NPREV + h) * 1024 + l) * 64;
        float* v = g_V + base;
        v[d]      = wmma::__float_to_tf32(pv[d]);
        v[d + 32] = wmma::__float_to_tf32(pv[d + 32]);
    }
}

// ---------------------------------------------------------------------------
// Flash attention: BR=128, BC=64, 512 threads (16 warps, 4x4 layout).
// Per-row numerics identical to BR=64 version (same KV tile sequence).
// ---------------------------------------------------------------------------
#define FLD  68
#define CTLD 20
// Qs 128 + Ks 64 + Vs 64 + Ss 128 rows of FLD, + Ct 128 x CTLD
#define FSM  (((128 + 64 + 64 + 128) * FLD + 128 * CTLD) * 4)

__global__ void __launch_bounds__(512, 1) flash_wmma(
    const float* __restrict__ Q, const float* __restrict__ K,
    const float* __restrict__ V, float* __restrict__ AO)
{
    extern __shared__ float sm[];
    float* Qs = sm;                   // 128 x FLD
    float* Ks = sm + 128 * FLD;       // 64 x FLD
    float* Vs = sm + 192 * FLD;       // 64 x FLD
    float* Ss = sm + 256 * FLD;       // 128 x FLD (scores -> P; O at end)
    float* Ct = sm + 384 * FLD;       // 128 x CTLD

    const int t    = threadIdx.x;
    const int warp = t >> 5;
    const int wm   = warp & 3;   // row group: 32*wm .. +31
    const int wn   = warp >> 2;  // col group: 16*wn .. +15
    const int qt   = blockIdx.x;
    const int h    = blockIdx.y;
    const int b    = blockIdx.z;
    const int q0   = qt * 128;

    const size_t bh_off = (size_t)(b * 32 + h) * 1024 * 64;
    const float* Qp = Q + bh_off;
    const float* Kp = K + bh_off;
    const float* Vp = V + bh_off;

    // KV loaders: 64x64 tile = 1024 float4, 2 per thread
    float4 rk[2], rv[2];
    int fr[2], fc[2];
#pragma unroll
    for (int q = 0; q < 2; q++) {
        int f = q * 512 + t;
        fr[q] = f >> 4; fc[q] = (f & 15) * 4;
    }
    auto kv_ldg = [&](int j) {
#pragma unroll
        for (int q = 0; q < 2; q++) {
            size_t goff = (size_t)(j * 64 + fr[q]) * 64 + fc[q];
            rk[q] = *(const float4*)(Kp + goff);
            rv[q] = *(const float4*)(Vp + goff);
        }
    };
    auto kv_sts = [&]() {
#pragma unroll
        for (int q = 0; q < 2; q++) {
            *(float4*)(Ks + fr[q] * FLD + fc[q]) = rk[q];
            *(float4*)(Vs + fr[q] * FLD + fc[q]) = rv[q];
        }
    };

    // Q tile: 128x64 = 2048 float4, 4 per thread
#pragma unroll
    for (int q = 0; q < 4; q++) {
        int f = q * 512 + t;
        int r = f >> 4, c = (f & 15) * 4;
        float4 v = *(const float4*)(Qp + (size_t)(q0 + r) * 64 + c);
        *(float4*)(Qs + r * FLD + c) = v;
    }
    kv_ldg(0);
    kv_sts();
    __syncthreads();

    wmma::fragment<wmma::accumulator, 16, 16, 8, float> oacc[2];
#pragma unroll
    for (int n = 0; n < 2; n++) wmma::fill_fragment(oacc[n], 0.0f);

    const int srow = t >> 2;          // 0..127
    const int scol = (t & 3) * 16;
    float m_r = -1e30f, l_r = 0.0f;

    const int njt = 2 * qt + 2;       // KV tiles covering keys <= q0+127
    for (int j = 0; j < njt; j++) {
        if (j + 1 < njt) kv_ldg(j + 1);

        // S = Q @ K^T : warp -> S[32*wm..+31, 16*wn..+15]
        {
            wmma::fragment<wmma::accumulator, 16, 16, 8, float> sacc[2];
#pragma unroll
            for (int n = 0; n < 2; n++) wmma::fill_fragment(sacc[n], 0.0f);
#pragma unroll
            for (int ks = 0; ks < 8; ks++) {
                wmma::fragment<wmma::matrix_b, 16, 16, 8, wmma::precision::tf32,
                               wmma::col_major> bf;
                wmma::load_matrix_sync(bf, Ks + (wn * 16) * FLD + ks * 8, FLD);
#pragma unroll
                for (int n = 0; n < 2; n++) {
                    wmma::fragment<wmma::matrix_a, 16, 16, 8, wmma::precision::tf32,
                                   wmma::row_major> af;
                    wmma::load_matrix_sync(af,
                        Qs + (wm * 32 + n * 16) * FLD + ks * 8, FLD);
                    wmma::mma_sync(sacc[n], af, bf, sacc[n]);
                }
            }
#pragma unroll
            for (int n = 0; n < 2; n++)
                wmma::store_matrix_sync(Ss + (wm * 32 + n * 16) * FLD + wn * 16,
                                        sacc[n], FLD, wmma::mem_row_major);
        }
        __syncthreads();

        // Online softmax (4 threads/row, rows 0..127)
        {
            float sv[16];
#pragma unroll
            for (int i4 = 0; i4 < 4; i4++) {
                float4 v = *(const float4*)(Ss + srow * FLD + scol + i4 * 4);
                sv[i4 * 4 + 0] = v.x * 0.125f;
                sv[i4 * 4 + 1] = v.y * 0.125f;
                sv[i4 * 4 + 2] = v.z * 0.125f;
                sv[i4 * 4 + 3] = v.w * 0.125f;
            }
            if (j >= 2 * qt) {   // boundary tiles: causal mask
                int key0 = j * 64 + scol;
                int qrow = q0 + srow;
#pragma unroll
                for (int i = 0; i < 16; i++)
                    if (key0 + i > qrow) sv[i] = -1e30f;
            }
            float mx = sv[0];
#pragma unroll
            for (int i = 1; i < 16; i++) mx = fmaxf(mx, sv[i]);
            mx = fmaxf(mx, __shfl_xor_sync(0xffffffffu, mx, 1));
            mx = fmaxf(mx, __shfl_xor_sync(0xffffffffu, mx, 2));
            float mnew = fmaxf(m_r, mx);
            float corr = __expf(m_r - mnew);
            float rs = 0.0f;
#pragma unroll
            for (int i = 0; i < 16; i++) {
                sv[i] = __expf(sv[i] - mnew);
                rs += sv[i];
            }
            rs += __shfl_xor_sync(0xffffffffu, rs, 1);
            rs += __shfl_xor_sync(0xffffffffu, rs, 2);
            l_r = l_r * corr + rs;
            m_r = mnew;
#pragma unroll
            for (int i4 = 0; i4 < 4; i4++) {
                float4 p;
                p.x = wmma::__float_to_tf32(sv[i4 * 4 + 0]);
                p.y = wmma::__float_to_tf32(sv[i4 * 4 + 1]);
                p.z = wmma::__float_to_tf32(sv[i4 * 4 + 2]);
                p.w = wmma::__float_to_tf32(sv[i4 * 4 + 3]);
                *(float4*)(Ss + srow * FLD + scol + i4 * 4) = p;
            }
            float* cd = Ct + srow * CTLD + (t & 3) * 4;
            cd[0] = corr; cd[1] = corr; cd[2] = corr; cd[3] = corr;
        }
        __syncthreads();

        // O *= corr; O += P @ V  (warp -> O[32*wm..+31, 16*wn..+15])
        {
            wmma::fragment<wmma::accumulator, 16, 16, 8, float> cf[2];
#pragma unroll
            for (int n = 0; n < 2; n++) {
                wmma::load_matrix_sync(cf[n], Ct + (wm * 32 + n * 16) * CTLD,
                                       CTLD, wmma::mem_row_major);
#pragma unroll
                for (int e = 0; e < cf[n].num_elements; e++)
                    oacc[n].x[e] *= cf[n].x[e];
            }
#pragma unroll
            for (int ks = 0; ks < 8; ks++) {
                wmma::fragment<wmma::matrix_b, 16, 16, 8, wmma::precision::tf32,
                               wmma::row_major> bf;
                wmma::load_matrix_sync(bf, Vs + (ks * 8) * FLD + wn * 16, FLD);
#pragma unroll
                for (int n = 0; n < 2; n++) {
                    wmma::fragment<wmma::matrix_a, 16, 16, 8, wmma::precision::tf32,
                                   wmma::row_major> af;
                    wmma::load_matrix_sync(af,
                        Ss + (wm * 32 + n * 16) * FLD + ks * 8, FLD);
                    wmma::mma_sync(oacc[n], af, bf, oacc[n]);
                }
            }
        }
        __syncthreads();

        if (j + 1 < njt) {
            kv_sts();
            __syncthreads();
        }
    }

    // Epilogue: O frags -> Ss, normalize, write AO (tf32-rounded)
#pragma unroll
    for (int n = 0; n < 2; n++)
        wmma::store_matrix_sync(Ss + (wm * 32 + n * 16) * FLD + wn * 16,
                                oacc[n], FLD, wmma::mem_row_major);
    __syncthreads();
    {
        float rl = 1.0f / l_r;
        size_t row = (size_t)b * 1024 + (q0 + srow);
        float* dst = AO + row * 2048 + h * 64 + scol;
#pragma unroll
        for (int i4 = 0; i4 < 4; i4++) {
            float4 o = *(const float4*)(Ss + srow * FLD + scol + i4 * 4);
            o.x = wmma::__float_to_tf32(o.x * rl);
            o.y = wmma::__float_to_tf32(o.y * rl);
            o.z = wmma::__float_to_tf32(o.z * rl);
            o.w = wmma::__float_to_tf32(o.w * rl);
            *(float4*)(dst + i4 * 4) = o;
        }
    }
}

// ---------------------------------------------------------------------------
// Launch
// ---------------------------------------------------------------------------
extern "C" void kernel_launch(void* const* d_in, const int* in_sizes, int n_in,
                              void* d_out, int out_size)
{
    const float* hs   = (const float*)d_in[0];
    const float* pk   = (const float*)d_in[1];
    const float* pv   = (const float*)d_in[2];
    const float* Wq   = (const float*)d_in[3];
    const float* Wk   = (const float*)d_in[4];
    const float* Wv   = (const float*)d_in[5];
    const float* Wo   = (const float*)d_in[6];
    const float* cosp = (const float*)d_in[7];
    const float* sinp = (const float*)d_in[8];
    float* out = (float*)d_out;

    float *Qb, *Kb, *Vb, *AO, *hsT, *WqT, *WkT, *WvT, *WoT;
    cudaGetSymbolAddress((void**)&Qb,  g_Q);
    cudaGetSymbolAddress((void**)&Kb,  g_K);
    cudaGetSymbolAddress((void**)&Vb,  g_V);
    cudaGetSymbolAddress((void**)&AO,  g_AO);
    cudaGetSymbolAddress((void**)&hsT, g_hsT);
    cudaGetSymbolAddress((void**)&WqT, g_WqT);
    cudaGetSymbolAddress((void**)&WkT, g_WkT);
    cudaGetSymbolAddress((void**)&WvT, g_WvT);
    cudaGetSymbolAddress((void**)&WoT, g_WoT);

    const int smem_g128 = 4 * (128 + 128) * LDS * 4;
    const int smem_g64  = 4 * (64 + 128) * LDS * 4;

    cudaFuncSetAttribute((const void*)gemm_ca<128, 128, 4, 2, 1>,
                         cudaFuncAttributeMaxDynamicSharedMemorySize, smem_g128);
    cudaFuncSetAttribute((const void*)gemm_ca<128, 128, 4, 2, 0>,
                         cudaFuncAttributeMaxDynamicSharedMemorySize, smem_g128);
    cudaFuncSetAttribute((const void*)gemm_ca<64, 128, 2, 4, 2>,
                         cudaFuncAttributeMaxDynamicSharedMemorySize, smem_g64);
    cudaFuncSetAttribute(flash_wmma,
                         cudaFuncAttributeMaxDynamicSharedMemorySize, FSM);

    const int NE_HS = BB * LL * HH / 4;
    const int NE_WQ = NQ * HD * HH / 4;
    const int NE_WK = NK * HD * HH / 4;
    const int NE_WO = HH * NQ * HD / 4;
    cvt_tf32<<<2048, 256>>>((const float4*)hs, (float4*)hsT, NE_HS);
    cvt_tf32<<<2048, 256>>>((const float4*)Wq, (float4*)WqT, NE_WQ);
    cvt_tf32<<<512,  256>>>((const float4*)Wk, (float4*)WkT, NE_WK);
    cvt_tf32<<<512,  256>>>((const float4*)Wv, (float4*)WvT, NE_WK);
    cvt_tf32<<<2048, 256>>>((const float4*)Wo, (float4*)WoT, NE_WO);

    // Q projection
    gemm_ca<128, 128, 4, 2, 1><<<dim3(16, 16), 256, smem_g128>>>(
        hsT, WqT, nullptr, Qb, nullptr, 2048, 2048, 2048);
    // Fused K+V projection
    gemm_ca<64, 128, 2, 4, 2><<<dim3(4, 32), 256, smem_g64>>>(
        hsT, WkT, WvT, Kb, Vb, 2048, 512, 2048);

    // Cache gather + RoPE
    rope_gather_kernel<<<8192, 256>>>(pk, pv, cosp, sinp);

    // Causal flash attention: BR=128, 512 threads, grid (8, 32, 2)
    flash_wmma<<<dim3(8, 32, 2), 512, FSM>>>(Qb, Kb, Vb, AO);

    // Output projection
    gemm_ca<128, 128, 4, 2, 0><<<dim3(16, 16), 256, smem_g128>>>(
        AO, WoT, nullptr, out, nullptr, 2048, 2048, 2048);
}

// round 17
// speedup vs baseline: 3.3369x; 3.3369x over previous
#include <cuda_runtime.h>
#include <cuda_fp16.h>
#include <mma.h>
#include <cstdint>
#include <cstddef>

using namespace nvcuda;

// Problem constants
#define BB 2
#define LL 1024
#define HH 2048
#define HD 64
#define NQ 32
#define NK 4
#define NPREV 28

// Scratch (device globals) — fp16 activations
__device__ __half g_Q[(size_t)BB * NQ * LL * HD];
__device__ __half g_K[(size_t)BB * NQ * LL * HD];
__device__ __half g_V[(size_t)BB * NQ * LL * HD];
__device__ __half g_AO[(size_t)BB * LL * (NQ * HD)];
__device__ __half g_hsT[(size_t)BB * LL * HH];
__device__ __half g_WqT[(size_t)NQ * HD * HH];
__device__ __half g_WkT[(size_t)NK * HD * HH];
__device__ __half g_WvT[(size_t)NK * HD * HH];
__device__ __half g_WoT[(size_t)HH * NQ * HD];

// ---------------------------------------------------------------------------
// cp.async helpers
// ---------------------------------------------------------------------------
__device__ __forceinline__ void cp_async16(uint32_t smem, const void* gmem) {
    asm volatile("cp.async.cg.shared.global [%0], [%1], 16;\n"
                 :: "r"(smem), "l"(gmem));
}
__device__ __forceinline__ void cp_commit() {
    asm volatile("cp.async.commit_group;\n" ::: "memory");
}
template<int N> __device__ __forceinline__ void cp_wait() {
    asm volatile("cp.async.wait_group %0;\n" :: "n"(N) : "memory");
}

// ---------------------------------------------------------------------------
// fp32 -> fp16 convert kernel (RN)
// ---------------------------------------------------------------------------
__global__ void cvt_fp16(const float4* __restrict__ src, __half2* __restrict__ dst,
                         int n4)
{
    int i = blockIdx.x * blockDim.x + threadIdx.x;
    int stride = gridDim.x * blockDim.x;
    for (; i < n4; i += stride) {
        float4 v = src[i];
        dst[i * 2 + 0] = __floats2half2_rn(v.x, v.y);
        dst[i * 2 + 1] = __floats2half2_rn(v.z, v.w);
    }
}

// ---------------------------------------------------------------------------
// 4-stage cp.async FP16 GEMM (fp32 accumulate): C = A @ W^T.
// A:[M,K] fp16 rm, W:[N,K] fp16 rm. BK=32, m16n16k16.
// MODE 0: C1 = float*, plain row-major store.
// MODE 1: Q scatter -> (__half*)C1 at [((b*32+h)*1024+l)*64+d]
// MODE 2: fused KV: col<256 W1 -> (__half*)C1 (K, head NPREV+h),
//                   col>=256 W2 -> (__half*)C2 (V, head NPREV+h-4)
// ---------------------------------------------------------------------------
#define LDSH 40   // halfs: 32 + 8 pad; rows 80B, 16B-aligned

template<int BM, int BN, int WM, int WN, int MODE>
__global__ void __launch_bounds__(256, 2) gemm_ca(
    const __half* __restrict__ A, const __half* __restrict__ W1,
    const __half* __restrict__ W2, void* __restrict__ C1,
    void* __restrict__ C2, int M, int N, int K)
{
    constexpr int S    = 4;
    constexpr int MI   = BM / (16 * WM);
    constexpr int NJ   = BN / (16 * WN);
    constexpr int APT  = BM * 4 / 256;   // 16B chunks per thread per A stage
    constexpr int BPT  = BN * 4 / 256;
    constexpr int ABUF = BM * LDSH;      // halfs per A stage
    constexpr int BBUF = BN * LDSH;

    extern __shared__ __align__(16) char gsm_raw[];
    __half* As = (__half*)gsm_raw;
    __half* Bs = As + S * ABUF;

    const int t    = threadIdx.x;
    const int warp = t >> 5;
    const int lane = t & 31;
    const int wm   = warp % WM;
    const int wn   = warp / WM;
    const int row0 = blockIdx.y * BM;
    const int col0 = blockIdx.x * BN;

    const __half* aptr[APT];
    uint32_t aoff[APT];
#pragma unroll
    for (int q = 0; q < APT; q++) {
        int f = q * 256 + t;
        int r = f >> 2, c = (f & 3) * 8;      // 4 chunks of 8 halfs per 32-col row
        aptr[q] = A + (size_t)(row0 + r) * K + c;
        aoff[q] = (uint32_t)__cvta_generic_to_shared(&As[r * LDSH + c]);
    }
    const __half* bptr[BPT];
    uint32_t boff[BPT];
#pragma unroll
    for (int q = 0; q < BPT; q++) {
        int f = q * 256 + t;
        int r = f >> 2, c = (f & 3) * 8;
        int rw = col0 + r;
        const __half* src;
        if (MODE == 2) src = (rw < 256) ? (W1 + (size_t)rw * K)
                                        : (W2 + (size_t)(rw - 256) * K);
        else           src = W1 + (size_t)rw * K;
        bptr[q] = src + c;
        boff[q] = (uint32_t)__cvta_generic_to_shared(&Bs[r * LDSH + c]);
    }

    wmma::fragment<wmma::accumulator, 16, 16, 16, float> acc[MI][NJ];
#pragma unroll
    for (int i = 0; i < MI; i++)
#pragma unroll
        for (int j = 0; j < NJ; j++) wmma::fill_fragment(acc[i][j], 0.0f);

    auto issue = [&](int chunk) {
        int st = chunk & (S - 1);
        int bk = chunk * 32;
#pragma unroll
        for (int q = 0; q < APT; q++)
            cp_async16(aoff[q] + st * ABUF * 2, aptr[q] + bk);
#pragma unroll
        for (int q = 0; q < BPT; q++)
            cp_async16(boff[q] + st * BBUF * 2, bptr[q] + bk);
    };
    auto compute = [&](int st) {
        const __half* Ab = As + st * ABUF;
        const __half* Bb = Bs + st * BBUF;
#pragma unroll
        for (int ks = 0; ks < 2; ks++) {
            wmma::fragment<wmma::matrix_a, 16, 16, 16, half, wmma::row_major> af[MI];
#pragma unroll
            for (int i = 0; i < MI; i++)
                wmma::load_matrix_sync(af[i],
                    Ab + (wm * MI + i) * 16 * LDSH + ks * 16, LDSH);
#pragma unroll
            for (int j = 0; j < NJ; j++) {
                wmma::fragment<wmma::matrix_b, 16, 16, 16, half, wmma::col_major> bf;
                wmma::load_matrix_sync(bf,
                    Bb + (wn * NJ + j) * 16 * LDSH + ks * 16, LDSH);
#pragma unroll
                for (int i = 0; i < MI; i++)
                    wmma::mma_sync(acc[i][j], af[i], bf, acc[i][j]);
            }
        }
    };

    const int nit = K / 32;
    issue(0); cp_commit();
    issue(1); cp_commit();
    issue(2); cp_commit();
    for (int i = 0; i < nit; i++) {
        cp_wait<S - 2>();
        __syncthreads();
        if (i + S - 1 < nit) issue(i + S - 1);
        cp_commit();
        compute(i & (S - 1));
    }

    // Epilogue
    if (MODE == 0) {
        float* C = (float*)C1;
#pragma unroll
        for (int i = 0; i < MI; i++) {
            int m0 = row0 + (wm * MI + i) * 16;
#pragma unroll
            for (int j = 0; j < NJ; j++) {
                int n0 = col0 + (wn * NJ + j) * 16;
                wmma::store_matrix_sync(C + (size_t)m0 * N + n0, acc[i][j], N,
                                        wmma::mem_row_major);
            }
        }
    } else {
        // fp16 scatter via per-warp smem staging (16x20 floats each)
        __syncthreads();   // all stage-buffer reads done before reuse
        float* sw = (float*)gsm_raw + warp * 320;
#pragma unroll
        for (int i = 0; i < MI; i++) {
            int m0 = row0 + (wm * MI + i) * 16;
#pragma unroll
            for (int j = 0; j < NJ; j++) {
                int n0 = col0 + (wn * NJ + j) * 16;
                wmma::store_matrix_sync(sw, acc[i][j], 20, wmma::mem_row_major);
                __syncwarp();
                __half* dstbase;
                {
                    int b = m0 >> 10, l = m0 & 1023;
                    int d = n0 & 63;
                    if (MODE == 1) {
                        int h = n0 >> 6;
                        dstbase = (__half*)C1 +
                            ((size_t)((b * 32 + h) * 1024 + l)) * 64 + d;
                    } else {
                        int h = n0 >> 6;
                        if (h < 4)
                            dstbase = (__half*)C1 +
                                ((size_t)((b * 32 + NPREV + h) * 1024 + l)) * 64 + d;
                        else
                            dstbase = (__half*)C2 +
                                ((size_t)((b * 32 + NPREV + h - 4) * 1024 + l)) * 64 + d;
                    }
                }
#pragma unroll
                for (int e = 0; e < 4; e++) {
                    int idx = lane * 4 + e;        // 0..127 half2 slots
                    int r = idx >> 3, c2 = idx & 7;
                    float v0 = sw[r * 20 + c2 * 2];
                    float v1 = sw[r * 20 + c2 * 2 + 1];
                    *(__half2*)(dstbase + (size_t)r * 64 + c2 * 2) =
                        __floats2half2_rn(v0, v1);
                }
                __syncwarp();
            }
        }
    }
}

// ---------------------------------------------------------------------------
// RoPE + cache gather (fp16 in/out for Q/K/V; fp32 math)
// ---------------------------------------------------------------------------
__global__ void __launch_bounds__(256) rope_gather_kernel(
    const float* __restrict__ prev_k, const float* __restrict__ prev_v,
    const float* __restrict__ cosp,   const float* __restrict__ sinp)
{
    unsigned t = blockIdx.x * 256u + threadIdx.x;
    int d = t & 31;
    int l = (t >> 5) & 1023;
    int h = (t >> 15) & 31;
    int b = t >> 20;

    float c = cosp[l * 64 + d];
    float s = sinp[l * 64 + d];

    size_t base = ((size_t)(b * 32 + h) * 1024 + l) * 64;

    {
        __half* q = g_Q + base;
        float x1 = __half2float(q[d]), x2 = __half2float(q[d + 32]);
        q[d]      = __float2half_rn(x1 * c - x2 * s);
        q[d + 32] = __float2half_rn(x2 * c + x1 * s);
    }
    {
        __half* k = g_K + base;
        float y1, y2;
        if (h < NPREV) {
            const float* pk = prev_k + ((size_t)(b * NPREV + h) * 1024 + l) * 64;
            y1 = pk[d]; y2 = pk[d + 32];
        } else {
            y1 = __half2float(k[d]); y2 = __half2float(k[d + 32]);
        }
        k[d]      = __float2half_rn(y1 * c - y2 * s);
        k[d + 32] = __float2half_rn(y2 * c + y1 * s);
    }
    if (h < NPREV) {
        const float* pv = prev_v + ((size_t)(b * NPREV + h) * 1024 + l) * 64;
        __half* v = g_V + base;
        v[d]      = __float2half_rn(pv[d]);
        v[d + 32] = __float2half_rn(pv[d + 32]);
    }
}

// ---------------------------------------------------------------------------
// Flash attention fp16 (m16n16k16, fp32 accum), BR=BC=64, 256 threads.
// Same structure as the proven R13/R15 kernel.
// ---------------------------------------------------------------------------
#define FLDH 72   // halfs per row (64 + 8 pad), 144B
#define SLD  68   // floats per row for scores
#define CTLD 20
#define FSM  (3 * 64 * FLDH * 2 + 64 * SLD * 4 + 64 * CTLD * 4 + 64 * FLDH * 2)

__global__ void __launch_bounds__(256, 2) flash_wmma(
    const __half* __restrict__ Q, const __half* __restrict__ K,
    const __half* __restrict__ V, __half* __restrict__ AO)
{
    extern __shared__ __align__(16) char fsm_raw[];
    __half* Qs = (__half*)fsm_raw;            // 64 x FLDH
    __half* Ks = Qs + 64 * FLDH;
    __half* Vs = Ks + 64 * FLDH;
    float*  Ss = (float*)(Vs + 64 * FLDH);    // 64 x SLD (fp32 scores)
    float*  Ct = Ss + 64 * SLD;               // 64 x CTLD
    __half* Ps = (__half*)(Ct + 64 * CTLD);   // 64 x FLDH (fp16 P)

    const int t    = threadIdx.x;
    const int warp = t >> 5;
    const int wm   = warp & 3;   // rows 16*wm..+15
    const int wn   = warp >> 2;  // cols 32*wn..+31
    const int qt   = blockIdx.x;
    const int h    = blockIdx.y;
    const int b    = blockIdx.z;
    const int q0   = qt * 64;

    const size_t bh_off = (size_t)(b * 32 + h) * 1024 * 64;
    const __half* Qp = Q + bh_off;
    const __half* Kp = K + bh_off;
    const __half* Vp = V + bh_off;

    // 64x64 halfs = 512 16B-chunks; 2 per thread
    float4 rk[2], rv[2];
    int fr[2], fc[2];
#pragma unroll
    for (int q = 0; q < 2; q++) {
        int f = q * 256 + t;
        fr[q] = f >> 3; fc[q] = (f & 7) * 8;
    }
    auto kv_ldg = [&](int j) {
#pragma unroll
        for (int q = 0; q < 2; q++) {
            size_t goff = (size_t)(j * 64 + fr[q]) * 64 + fc[q];
            rk[q] = *(const float4*)(Kp + goff);
            rv[q] = *(const float4*)(Vp + goff);
        }
    };
    auto kv_sts = [&]() {
#pragma unroll
        for (int q = 0; q < 2; q++) {
            *(float4*)(Ks + fr[q] * FLDH + fc[q]) = rk[q];
            *(float4*)(Vs + fr[q] * FLDH + fc[q]) = rv[q];
        }
    };

#pragma unroll
    for (int q = 0; q < 2; q++) {
        float4 v = *(const float4*)(Qp + (size_t)(q0 + fr[q]) * 64 + fc[q]);
        *(float4*)(Qs + fr[q] * FLDH + fc[q]) = v;
    }
    kv_ldg(0);
    kv_sts();
    __syncthreads();

    wmma::fragment<wmma::accumulator, 16, 16, 16, float> oacc[2];
#pragma unroll
    for (int n = 0; n < 2; n++) wmma::fill_fragment(oacc[n], 0.0f);

    const int srow = t >> 2;
    const int scol = (t & 3) * 16;
    float m_r = -1e30f, l_r = 0.0f;

    for (int j = 0; j <= qt; j++) {
        if (j < qt) kv_ldg(j + 1);

        // S = Q @ K^T
        {
            wmma::fragment<wmma::accumulator, 16, 16, 16, float> sacc[2];
#pragma unroll
            for (int n = 0; n < 2; n++) wmma::fill_fragment(sacc[n], 0.0f);
#pragma unroll
            for (int ks = 0; ks < 4; ks++) {
                wmma::fragment<wmma::matrix_a, 16, 16, 16, half, wmma::row_major> af;
                wmma::load_matrix_sync(af, Qs + (wm * 16) * FLDH + ks * 16, FLDH);
#pragma unroll
                for (int n = 0; n < 2; n++) {
                    wmma::fragment<wmma::matrix_b, 16, 16, 16, half, wmma::col_major> bf;
                    wmma::load_matrix_sync(bf,
                        Ks + (wn * 32 + n * 16) * FLDH + ks * 16, FLDH);
                    wmma::mma_sync(sacc[n], af, bf, sacc[n]);
                }
            }
#pragma unroll
            for (int n = 0; n < 2; n++)
                wmma::store_matrix_sync(Ss + (wm * 16) * SLD + wn * 32 + n * 16,
                                        sacc[n], SLD, wmma::mem_row_major);
        }
        __syncthreads();

        // Online softmax (4 threads/row)
        {
            float sv[16];
#pragma unroll
            for (int i4 = 0; i4 < 4; i4++) {
                float4 v = *(const float4*)(Ss + srow * SLD + scol + i4 * 4);
                sv[i4 * 4 + 0] = v.x * 0.125f;
                sv[i4 * 4 + 1] = v.y * 0.125f;
                sv[i4 * 4 + 2] = v.z * 0.125f;
                sv[i4 * 4 + 3] = v.w * 0.125f;
            }
            if (j == qt) {
#pragma unroll
                for (int i = 0; i < 16; i++)
                    if (scol + i > srow) sv[i] = -1e30f;
            }
            float mx = sv[0];
#pragma unroll
            for (int i = 1; i < 16; i++) mx = fmaxf(mx, sv[i]);
            mx = fmaxf(mx, __shfl_xor_sync(0xffffffffu, mx, 1));
            mx = fmaxf(mx, __shfl_xor_sync(0xffffffffu, mx, 2));
            float mnew = fmaxf(m_r, mx);
            float corr = __expf(m_r - mnew);
            float rs = 0.0f;
#pragma unroll
            for (int i = 0; i < 16; i++) {
                sv[i] = __expf(sv[i] - mnew);
                rs += sv[i];
            }
            rs += __shfl_xor_sync(0xffffffffu, rs, 1);
            rs += __shfl_xor_sync(0xffffffffu, rs, 2);
            l_r = l_r * corr + rs;
            m_r = mnew;
            // P (fp16) to Ps
#pragma unroll
            for (int e = 0; e < 8; e++)
                *(__half2*)(Ps + srow * FLDH + scol + e * 2) =
                    __floats2half2_rn(sv[e * 2], sv[e * 2 + 1]);
            float* cd = Ct + srow * CTLD + (t & 3) * 4;
            cd[0] = corr; cd[1] = corr; cd[2] = corr; cd[3] = corr;
        }
        __syncthreads();

        // O *= corr; O += P @ V
        {
            wmma::fragment<wmma::accumulator, 16, 16, 16, float> cf;
            wmma::load_matrix_sync(cf, Ct + (wm * 16) * CTLD, CTLD,
                                   wmma::mem_row_major);
#pragma unroll
            for (int n = 0; n < 2; n++)
#pragma unroll
                for (int e = 0; e < cf.num_elements; e++)
                    oacc[n].x[e] *= cf.x[e];

#pragma unroll
            for (int ks = 0; ks < 4; ks++) {
                wmma::fragment<wmma::matrix_a, 16, 16, 16, half, wmma::row_major> af;
                wmma::load_matrix_sync(af, Ps + (wm * 16) * FLDH + ks * 16, FLDH);
#pragma unroll
                for (int n = 0; n < 2; n++) {
                    wmma::fragment<wmma::matrix_b, 16, 16, 16, half, wmma::row_major> bf;
                    wmma::load_matrix_sync(bf,
                        Vs + (ks * 16) * FLDH + wn * 32 + n * 16, FLDH);
                    wmma::mma_sync(oacc[n], af, bf, oacc[n]);
                }
            }
        }
        __syncthreads();

        if (j < qt) {
            kv_sts();
            __syncthreads();
        }
    }

    // Epilogue: O frags -> Ss (fp32), normalize, write AO (fp16)
#pragma unroll
    for (int n = 0; n < 2; n++)
        wmma::store_matrix_sync(Ss + (wm * 16) * SLD + wn * 32 + n * 16,
                                oacc[n], SLD, wmma::mem_row_major);
    __syncthreads();
    {
        float rl = 1.0f / l_r;
        size_t row = (size_t)b * 1024 + (q0 + srow);
        __half* dst = AO + row * 2048 + h * 64 + scol;
#pragma unroll
        for (int e = 0; e < 8; e++) {
            float v0 = Ss[srow * SLD + scol + e * 2] * rl;
            float v1 = Ss[srow * SLD + scol + e * 2 + 1] * rl;
            *(__half2*)(dst + e * 2) = __floats2half2_rn(v0, v1);
        }
    }
}

// ---------------------------------------------------------------------------
// Launch
// ---------------------------------------------------------------------------
extern "C" void kernel_launch(void* const* d_in, const int* in_sizes, int n_in,
                              void* d_out, int out_size)
{
    const float* hs   = (const float*)d_in[0];
    const float* pk   = (const float*)d_in[1];
    const float* pv   = (const float*)d_in[2];
    const float* Wq   = (const float*)d_in[3];
    const float* Wk   = (const float*)d_in[4];
    const float* Wv   = (const float*)d_in[5];
    const float* Wo   = (const float*)d_in[6];
    const float* cosp = (const float*)d_in[7];
    const float* sinp = (const float*)d_in[8];
    float* out = (float*)d_out;

    __half *Qb, *Kb, *Vb, *AO, *hsT, *WqT, *WkT, *WvT, *WoT;
    cudaGetSymbolAddress((void**)&Qb,  g_Q);
    cudaGetSymbolAddress((void**)&Kb,  g_K);
    cudaGetSymbolAddress((void**)&Vb,  g_V);
    cudaGetSymbolAddress((void**)&AO,  g_AO);
    cudaGetSymbolAddress((void**)&hsT, g_hsT);
    cudaGetSymbolAddress((void**)&WqT, g_WqT);
    cudaGetSymbolAddress((void**)&WkT, g_WkT);
    cudaGetSymbolAddress((void**)&WvT, g_WvT);
    cudaGetSymbolAddress((void**)&WoT, g_WoT);

    const int smem_g128 = 4 * (128 + 128) * LDSH * 2;  // 81920
    const int smem_g64  = 4 * (64 + 128) * LDSH * 2;   // 61440

    cudaFuncSetAttribute((const void*)gemm_ca<128, 128, 4, 2, 1>,
                         cudaFuncAttributeMaxDynamicSharedMemorySize, smem_g128);
    cudaFuncSetAttribute((const void*)gemm_ca<128, 128, 4, 2, 0>,
                         cudaFuncAttributeMaxDynamicSharedMemorySize, smem_g128);
    cudaFuncSetAttribute((const void*)gemm_ca<64, 128, 2, 4, 2>,
                         cudaFuncAttributeMaxDynamicSharedMemorySize, smem_g64);
    cudaFuncSetAttribute(flash_wmma,
                         cudaFuncAttributeMaxDynamicSharedMemorySize, FSM);

    const int NE_HS = BB * LL * HH / 4;
    const int NE_WQ = NQ * HD * HH / 4;
    const int NE_WK = NK * HD * HH / 4;
    const int NE_WO = HH * NQ * HD / 4;
    cvt_fp16<<<2048, 256>>>((const float4*)hs, (__half2*)hsT, NE_HS);
    cvt_fp16<<<2048, 256>>>((const float4*)Wq, (__half2*)WqT, NE_WQ);
    cvt_fp16<<<512,  256>>>((const float4*)Wk, (__half2*)WkT, NE_WK);
    cvt_fp16<<<512,  256>>>((const float4*)Wv, (__half2*)WvT, NE_WK);
    cvt_fp16<<<2048, 256>>>((const float4*)Wo, (__half2*)WoT, NE_WO);

    // Q projection (fp16)
    gemm_ca<128, 128, 4, 2, 1><<<dim3(16, 16), 256, smem_g128>>>(
        hsT, WqT, nullptr, Qb, nullptr, 2048, 2048, 2048);
    // Fused K+V projection
    gemm_ca<64, 128, 2, 4, 2><<<dim3(4, 32), 256, smem_g64>>>(
        hsT, WkT, WvT, Kb, Vb, 2048, 512, 2048);

    // Cache gather + RoPE (fp16)
    rope_gather_kernel<<<8192, 256>>>(pk, pv, cosp, sinp);

    // Causal flash attention (fp16) -> g_AO
    flash_wmma<<<dim3(16, 32, 2), 256, FSM>>>(Qb, Kb, Vb, AO);

    // Output projection: AO fp16 @ Wo fp16 -> out fp32
    gemm_ca<128, 128, 4, 2, 0><<<dim3(16, 16), 256, smem_g128>>>(
        AO, WoT, nullptr, out, nullptr, 2048, 2048, 2048);
}